// round 2
// baseline (speedup 1.0000x reference)
#include <cuda_runtime.h>
#include <math.h>

#define SEQ 4096
#define DIM 1024
#define NH  16
#define HD  64

// ---------------- device scratch (no allocation allowed) ----------------
__device__ float g_qkv[SEQ * 3 * DIM];     // QKV projection output
__device__ float g_Q[NH * SEQ * HD];       // roped, head-major
__device__ float g_K[NH * SEQ * HD];
__device__ float g_V[NH * SEQ * HD];
__device__ float g_O[SEQ * DIM];           // attention output (s, dim)
__device__ float g_att[SEQ * DIM];         // after out-proj, pre-LN
__device__ float g_cos[SEQ * 512];
__device__ float g_sin[SEQ * 512];

// ---------------- RoPE tables (double precision for accurate trig) ------
__global__ void rope_tables_kernel() {
    int idx = blockIdx.x * blockDim.x + threadIdx.x;
    if (idx >= SEQ * 512) return;
    int s = idx >> 9;
    int i = idx & 511;
    // inv_freq = 10000^{-i/512}, rounded to fp32 like the reference
    float invf = (float)exp(-((double)i) * (9.210340371976184 / 512.0));
    double ang = (double)s * (double)invf;
    g_cos[idx] = (float)cos(ang);
    g_sin[idx] = (float)sin(ang);
}

// ---------------- RoPE apply + scatter to head-major Q/K/V --------------
__global__ void rope_scatter_kernel() {
    int idx = blockIdx.x * blockDim.x + threadIdx.x;   // SEQ*DIM threads
    int s = idx >> 10;
    int j = idx & 1023;
    int i = j & 511;
    float c  = g_cos[(s << 9) + i];
    float sn = g_sin[(s << 9) + i];
    const float* row = g_qkv + (size_t)s * (3 * DIM);
    float q = row[j];
    float k = row[DIM + j];
    float v = row[2 * DIM + j];
    float q2, k2;
    if (j < 512) { q2 = -row[j + 512];       k2 = -row[DIM + j + 512]; }
    else         { q2 =  row[j - 512];       k2 =  row[DIM + j - 512]; }
    float qo = q * c + q2 * sn;
    float ko = k * c + k2 * sn;
    int h = j >> 6, d = j & 63;
    int o = ((h * SEQ) + s) * HD + d;
    g_Q[o] = qo;
    g_K[o] = ko;
    g_V[o] = v;
}

// ---------------- fp32 SGEMM core: C[M,N] = A[M,K] @ B[K,N] + bias ------
// 128x128 block tile, BK=8, 8x8 per-thread register tile, 256 threads.
__device__ __forceinline__
void sgemm_bias_body(int N, int K,
                     const float* __restrict__ A,
                     const float* __restrict__ B,
                     const float* __restrict__ bias,
                     float* __restrict__ C) {
    const int BM = 128, BK = 8, TM = 8, TN = 8;
    __shared__ float As[BK][BM];
    __shared__ float Bs[BK][128];
    int tid = threadIdx.x;
    int m0 = blockIdx.y * BM, n0 = blockIdx.x * 128;

    int aRow = tid >> 1, aCol = (tid & 1) * 4;
    int bRow = tid >> 5, bCol = (tid & 31) * 4;
    const float* Ag = A + (size_t)(m0 + aRow) * K + aCol;
    const float* Bg = B + (size_t)bRow * N + n0 + bCol;

    int tr = (tid >> 4) * TM;
    int tc = (tid & 15) * TN;

    float acc[TM][TN];
#pragma unroll
    for (int i = 0; i < TM; i++)
#pragma unroll
        for (int j = 0; j < TN; j++) acc[i][j] = 0.f;

    for (int k0 = 0; k0 < K; k0 += BK) {
        float4 a4 = *(const float4*)(Ag + k0);
        As[aCol + 0][aRow] = a4.x;
        As[aCol + 1][aRow] = a4.y;
        As[aCol + 2][aRow] = a4.z;
        As[aCol + 3][aRow] = a4.w;
        *(float4*)(&Bs[bRow][bCol]) = *(const float4*)(Bg + (size_t)k0 * N);
        __syncthreads();
#pragma unroll
        for (int k = 0; k < BK; k++) {
            float4 m0v = *(const float4*)(&As[k][tr]);
            float4 m1v = *(const float4*)(&As[k][tr + 4]);
            float4 n0v = *(const float4*)(&Bs[k][tc]);
            float4 n1v = *(const float4*)(&Bs[k][tc + 4]);
            float rm[TM] = {m0v.x, m0v.y, m0v.z, m0v.w, m1v.x, m1v.y, m1v.z, m1v.w};
            float rn[TN] = {n0v.x, n0v.y, n0v.z, n0v.w, n1v.x, n1v.y, n1v.z, n1v.w};
#pragma unroll
            for (int i = 0; i < TM; i++)
#pragma unroll
                for (int j = 0; j < TN; j++)
                    acc[i][j] = fmaf(rm[i], rn[j], acc[i][j]);
        }
        __syncthreads();
    }

    float4 bv0 = *(const float4*)(bias + n0 + tc);
    float4 bv1 = *(const float4*)(bias + n0 + tc + 4);
    float bb[TN] = {bv0.x, bv0.y, bv0.z, bv0.w, bv1.x, bv1.y, bv1.z, bv1.w};
    float* Cg = C + (size_t)(m0 + tr) * N + n0 + tc;
#pragma unroll
    for (int i = 0; i < TM; i++) {
#pragma unroll
        for (int j = 0; j < TN; j += 4) {
            float4 cv;
            cv.x = acc[i][j + 0] + bb[j + 0];
            cv.y = acc[i][j + 1] + bb[j + 1];
            cv.z = acc[i][j + 2] + bb[j + 2];
            cv.w = acc[i][j + 3] + bb[j + 3];
            *(float4*)(Cg + (size_t)i * N + j) = cv;
        }
    }
}

// QKV projection: A = x (input), C = g_qkv (device global)
__global__ __launch_bounds__(256)
void sgemm_qkv_kernel(const float* __restrict__ x,
                      const float* __restrict__ Wqkv,
                      const float* __restrict__ bqkv) {
    sgemm_bias_body(3 * DIM, DIM, x, Wqkv, bqkv, g_qkv);
}

// Output projection: A = g_O (device global), C = g_att (device global)
__global__ __launch_bounds__(256)
void sgemm_out_kernel(const float* __restrict__ Wo,
                      const float* __restrict__ bo) {
    sgemm_bias_body(DIM, DIM, g_O, Wo, bo, g_att);
}

// ---------------- causal flash attention -------------------------------
// grid (SEQ/128, NH), 128 threads, one query row per thread.
// K/V tiles of 64 rows in smem; scores in 32-key register chunks.
__global__ __launch_bounds__(128)
void flash_kernel() {
    __shared__ float Ks[64 * 64];
    __shared__ float Vs[64 * 64];
    int h = blockIdx.y;
    int m0 = blockIdx.x * 128;
    int tid = threadIdx.x;
    int m = m0 + tid;

    const float* Qr = g_Q + (size_t)((h * SEQ) + m) * HD;
    float q[64];
#pragma unroll
    for (int d4 = 0; d4 < 16; d4++) {
        float4 t = ((const float4*)Qr)[d4];
        q[4 * d4 + 0] = t.x; q[4 * d4 + 1] = t.y;
        q[4 * d4 + 2] = t.z; q[4 * d4 + 3] = t.w;
    }
    float o[64];
#pragma unroll
    for (int d = 0; d < 64; d++) o[d] = 0.f;
    float mx = -INFINITY, l = 0.f;

    int nT = blockIdx.x * 2 + 2;  // key tiles up to and including the diagonal
    for (int t = 0; t < nT; t++) {
        int j0 = t * 64;
        const float* Kt = g_K + (size_t)((h * SEQ) + j0) * HD;
        const float* Vt = g_V + (size_t)((h * SEQ) + j0) * HD;
#pragma unroll
        for (int r = 0; r < 8; r++) {
            int off = (r * 128 + tid) * 4;
            *(float4*)(Ks + off) = *(const float4*)(Kt + off);
            *(float4*)(Vs + off) = *(const float4*)(Vt + off);
        }
        __syncthreads();

#pragma unroll
        for (int c = 0; c < 2; c++) {
            int jb = j0 + c * 32;
            if (jb <= m) {
                float sreg[32];
                float tmax = -INFINITY;
#pragma unroll 4
                for (int j = 0; j < 32; j++) {
                    const float4* K4 = (const float4*)(Ks + (c * 32 + j) * 64);
                    float s = 0.f;
#pragma unroll
                    for (int d4 = 0; d4 < 16; d4++) {
                        float4 kv = K4[d4];
                        s = fmaf(q[4 * d4 + 0], kv.x, s);
                        s = fmaf(q[4 * d4 + 1], kv.y, s);
                        s = fmaf(q[4 * d4 + 2], kv.z, s);
                        s = fmaf(q[4 * d4 + 3], kv.w, s);
                    }
                    s *= 0.125f;
                    if (jb + j > m) s = -INFINITY;  // causal mask
                    sreg[j] = s;
                    tmax = fmaxf(tmax, s);
                }
                float mnew = fmaxf(mx, tmax);
                float corr = __expf(mx - mnew);
                mx = mnew;
                l *= corr;
#pragma unroll
                for (int d = 0; d < 64; d++) o[d] *= corr;
#pragma unroll 2
                for (int j = 0; j < 32; j++) {
                    float p = __expf(sreg[j] - mnew);
                    l += p;
                    const float4* V4 = (const float4*)(Vs + (c * 32 + j) * 64);
#pragma unroll
                    for (int d4 = 0; d4 < 16; d4++) {
                        float4 vv = V4[d4];
                        o[4 * d4 + 0] = fmaf(p, vv.x, o[4 * d4 + 0]);
                        o[4 * d4 + 1] = fmaf(p, vv.y, o[4 * d4 + 1]);
                        o[4 * d4 + 2] = fmaf(p, vv.z, o[4 * d4 + 2]);
                        o[4 * d4 + 3] = fmaf(p, vv.w, o[4 * d4 + 3]);
                    }
                }
            }
        }
        __syncthreads();
    }

    float inv = 1.f / l;
    float* Or = g_O + (size_t)m * DIM + h * HD;
#pragma unroll
    for (int d4 = 0; d4 < 16; d4++) {
        float4 t;
        t.x = o[4 * d4 + 0] * inv;
        t.y = o[4 * d4 + 1] * inv;
        t.z = o[4 * d4 + 2] * inv;
        t.w = o[4 * d4 + 3] * inv;
        ((float4*)Or)[d4] = t;
    }
}

// ---------------- LayerNorm over last dim (1024) ------------------------
__global__ __launch_bounds__(256)
void layernorm_kernel(const float* __restrict__ gamma,
                      const float* __restrict__ beta,
                      float* __restrict__ Y) {
    int r = blockIdx.x;
    const float* x = g_att + (size_t)r * DIM;
    int tid = threadIdx.x;

    float s = 0.f, s2 = 0.f;
#pragma unroll
    for (int it = 0; it < DIM / 256; it++) {
        float v = x[tid + it * 256];
        s += v;
        s2 += v * v;
    }
#pragma unroll
    for (int off = 16; off; off >>= 1) {
        s  += __shfl_xor_sync(0xffffffffu, s, off);
        s2 += __shfl_xor_sync(0xffffffffu, s2, off);
    }
    __shared__ float ws[8], ws2[8];
    int w = tid >> 5, lane = tid & 31;
    if (lane == 0) { ws[w] = s; ws2[w] = s2; }
    __syncthreads();
    float S1 = 0.f, S2 = 0.f;
#pragma unroll
    for (int i = 0; i < 8; i++) { S1 += ws[i]; S2 += ws2[i]; }

    float mu  = S1 * (1.f / DIM);
    float var = S2 * (1.f / DIM) - mu * mu;
    float inv = rsqrtf(var + 1e-5f);
#pragma unroll
    for (int it = 0; it < DIM / 256; it++) {
        int j = tid + it * 256;
        float v = x[j];
        Y[(size_t)r * DIM + j] = (v - mu) * inv * gamma[j] + beta[j];
    }
}

// ---------------- launch (pure kernel launches, no runtime API) ---------
extern "C" void kernel_launch(void* const* d_in, const int* in_sizes, int n_in,
                              void* d_out, int out_size) {
    const float* x     = (const float*)d_in[0];
    const float* Wqkv  = (const float*)d_in[1];
    const float* bqkv  = (const float*)d_in[2];
    const float* Wo    = (const float*)d_in[3];
    const float* bo    = (const float*)d_in[4];
    const float* gamma = (const float*)d_in[5];
    const float* beta  = (const float*)d_in[6];
    float* out = (float*)d_out;

    // 1) RoPE tables
    rope_tables_kernel<<<(SEQ * 512) / 256, 256>>>();
    // 2) QKV projection: (4096 x 3072) = x(4096x1024) @ Wqkv + bqkv
    sgemm_qkv_kernel<<<dim3(3 * DIM / 128, SEQ / 128), 256>>>(x, Wqkv, bqkv);
    // 3) RoPE + head-major scatter
    rope_scatter_kernel<<<(SEQ * DIM) / 256, 256>>>();
    // 4) causal flash attention
    flash_kernel<<<dim3(SEQ / 128, NH), 128>>>();
    // 5) output projection
    sgemm_out_kernel<<<dim3(DIM / 128, SEQ / 128), 256>>>(Wo, bo);
    // 6) LayerNorm -> final output
    layernorm_kernel<<<SEQ, 256>>>(gamma, beta, out);
}

// round 3
// speedup vs baseline: 1.3693x; 1.3693x over previous
#include <cuda_runtime.h>
#include <math.h>

#define SEQ 4096
#define DIM 1024
#define NH  16
#define HD  64
#define KT  32   // keys per flash tile

// ---------------- device scratch (no allocation allowed) ----------------
__device__ float g_qkv[SEQ * 3 * DIM];     // QKV projection output
__device__ float g_Q[NH * SEQ * HD];       // roped, head-major
__device__ float g_K[NH * SEQ * HD];
__device__ float g_V[NH * SEQ * HD];
__device__ float g_O[SEQ * DIM];           // attention output (s, dim)
__device__ float g_att[SEQ * DIM];         // after out-proj, pre-LN
__device__ float g_cos[SEQ * 512];
__device__ float g_sin[SEQ * 512];

// ---------------- RoPE tables (double precision for accurate trig) ------
__global__ void rope_tables_kernel() {
    int idx = blockIdx.x * blockDim.x + threadIdx.x;
    if (idx >= SEQ * 512) return;
    int s = idx >> 9;
    int i = idx & 511;
    float invf = (float)exp(-((double)i) * (9.210340371976184 / 512.0));
    double ang = (double)s * (double)invf;
    g_cos[idx] = (float)cos(ang);
    g_sin[idx] = (float)sin(ang);
}

// ---------------- RoPE apply + scatter to head-major Q/K/V --------------
__global__ void rope_scatter_kernel() {
    int idx = blockIdx.x * blockDim.x + threadIdx.x;   // SEQ*DIM threads
    int s = idx >> 10;
    int j = idx & 1023;
    int i = j & 511;
    float c  = g_cos[(s << 9) + i];
    float sn = g_sin[(s << 9) + i];
    const float* row = g_qkv + (size_t)s * (3 * DIM);
    float q = row[j];
    float k = row[DIM + j];
    float v = row[2 * DIM + j];
    float q2, k2;
    if (j < 512) { q2 = -row[j + 512];       k2 = -row[DIM + j + 512]; }
    else         { q2 =  row[j - 512];       k2 =  row[DIM + j - 512]; }
    float qo = q * c + q2 * sn;
    float ko = k * c + k2 * sn;
    int h = j >> 6, d = j & 63;
    int o = ((h * SEQ) + s) * HD + d;
    g_Q[o] = qo;
    g_K[o] = ko;
    g_V[o] = v;
}

// ---------------- fp32 SGEMM core (unchanged this round) ----------------
__device__ __forceinline__
void sgemm_bias_body(int N, int K,
                     const float* __restrict__ A,
                     const float* __restrict__ B,
                     const float* __restrict__ bias,
                     float* __restrict__ C) {
    const int BM = 128, BK = 8, TM = 8, TN = 8;
    __shared__ float As[BK][BM];
    __shared__ float Bs[BK][128];
    int tid = threadIdx.x;
    int m0 = blockIdx.y * BM, n0 = blockIdx.x * 128;

    int aRow = tid >> 1, aCol = (tid & 1) * 4;
    int bRow = tid >> 5, bCol = (tid & 31) * 4;
    const float* Ag = A + (size_t)(m0 + aRow) * K + aCol;
    const float* Bg = B + (size_t)bRow * N + n0 + bCol;

    int tr = (tid >> 4) * TM;
    int tc = (tid & 15) * TN;

    float acc[TM][TN];
#pragma unroll
    for (int i = 0; i < TM; i++)
#pragma unroll
        for (int j = 0; j < TN; j++) acc[i][j] = 0.f;

    for (int k0 = 0; k0 < K; k0 += BK) {
        float4 a4 = *(const float4*)(Ag + k0);
        As[aCol + 0][aRow] = a4.x;
        As[aCol + 1][aRow] = a4.y;
        As[aCol + 2][aRow] = a4.z;
        As[aCol + 3][aRow] = a4.w;
        *(float4*)(&Bs[bRow][bCol]) = *(const float4*)(Bg + (size_t)k0 * N);
        __syncthreads();
#pragma unroll
        for (int k = 0; k < BK; k++) {
            float4 m0v = *(const float4*)(&As[k][tr]);
            float4 m1v = *(const float4*)(&As[k][tr + 4]);
            float4 n0v = *(const float4*)(&Bs[k][tc]);
            float4 n1v = *(const float4*)(&Bs[k][tc + 4]);
            float rm[TM] = {m0v.x, m0v.y, m0v.z, m0v.w, m1v.x, m1v.y, m1v.z, m1v.w};
            float rn[TN] = {n0v.x, n0v.y, n0v.z, n0v.w, n1v.x, n1v.y, n1v.z, n1v.w};
#pragma unroll
            for (int i = 0; i < TM; i++)
#pragma unroll
                for (int j = 0; j < TN; j++)
                    acc[i][j] = fmaf(rm[i], rn[j], acc[i][j]);
        }
        __syncthreads();
    }

    float4 bv0 = *(const float4*)(bias + n0 + tc);
    float4 bv1 = *(const float4*)(bias + n0 + tc + 4);
    float bb[TN] = {bv0.x, bv0.y, bv0.z, bv0.w, bv1.x, bv1.y, bv1.z, bv1.w};
    float* Cg = C + (size_t)(m0 + tr) * N + n0 + tc;
#pragma unroll
    for (int i = 0; i < TM; i++) {
#pragma unroll
        for (int j = 0; j < TN; j += 4) {
            float4 cv;
            cv.x = acc[i][j + 0] + bb[j + 0];
            cv.y = acc[i][j + 1] + bb[j + 1];
            cv.z = acc[i][j + 2] + bb[j + 2];
            cv.w = acc[i][j + 3] + bb[j + 3];
            *(float4*)(Cg + (size_t)i * N + j) = cv;
        }
    }
}

__global__ __launch_bounds__(256)
void sgemm_qkv_kernel(const float* __restrict__ x,
                      const float* __restrict__ Wqkv,
                      const float* __restrict__ bqkv) {
    sgemm_bias_body(3 * DIM, DIM, x, Wqkv, bqkv, g_qkv);
}

__global__ __launch_bounds__(256)
void sgemm_out_kernel(const float* __restrict__ Wo,
                      const float* __restrict__ bo) {
    sgemm_bias_body(DIM, DIM, g_O, Wo, bo, g_att);
}

// ---------------- TF32 mma helpers --------------------------------------
__device__ __forceinline__ unsigned f2tf32(float x) {
    unsigned r;
    asm("cvt.rna.tf32.f32 %0, %1;" : "=r"(r) : "f"(x));
    return r;
}
__device__ __forceinline__ void mma_tf32(float* c, const unsigned* a, const unsigned* b) {
    asm volatile(
        "mma.sync.aligned.m16n8k8.row.col.f32.tf32.tf32.f32 "
        "{%0,%1,%2,%3}, {%4,%5,%6,%7}, {%8,%9}, {%0,%1,%2,%3};"
        : "+f"(c[0]), "+f"(c[1]), "+f"(c[2]), "+f"(c[3])
        : "r"(a[0]), "r"(a[1]), "r"(a[2]), "r"(a[3]), "r"(b[0]), "r"(b[1]));
}

// ---------------- causal flash attention, TF32 tensor cores -------------
// Block: 128 queries of one head, 256 threads = 8 warps, 16 queries/warp.
// Key tiles of KT=32. 3xTF32 on both QK^T and PV for fp32-grade accuracy.
__global__ __launch_bounds__(256, 1)
void flash_mma_kernel() {
    __shared__ float Kh[KT][68], Kl[KT][68];     // [key][dim], pad->conflict-free frags
    __shared__ float VTh[64][36], VTl[64][36];   // V^T [dim][key]

    int h = blockIdx.y;
    int m0 = blockIdx.x * 128;
    int tid = threadIdx.x;
    int w = tid >> 5, lane = tid & 31;
    int g = lane >> 2, c = lane & 3;             // groupID, thread-in-group
    int q0w = m0 + w * 16;

    // ---- Q fragments (pre-scaled by 1/8), hi/lo split, held in regs ----
    unsigned qh[8][4], ql[8][4];
    {
        const float* Qb = g_Q + ((size_t)h * SEQ + q0w) * HD;
#pragma unroll
        for (int kk = 0; kk < 8; kk++) {
            float v[4];
            v[0] = Qb[(size_t)g * HD + kk * 8 + c] * 0.125f;
            v[1] = Qb[(size_t)(g + 8) * HD + kk * 8 + c] * 0.125f;
            v[2] = Qb[(size_t)g * HD + kk * 8 + c + 4] * 0.125f;
            v[3] = Qb[(size_t)(g + 8) * HD + kk * 8 + c + 4] * 0.125f;
#pragma unroll
            for (int i = 0; i < 4; i++) {
                unsigned hi = f2tf32(v[i]);
                qh[kk][i] = hi;
                ql[kk][i] = __float_as_uint(v[i] - __uint_as_float(hi));
            }
        }
    }

    float o[8][4];
#pragma unroll
    for (int nn = 0; nn < 8; nn++)
#pragma unroll
        for (int i = 0; i < 4; i++) o[nn][i] = 0.f;
    float mrow[2] = {-INFINITY, -INFINITY};
    float lrow[2] = {0.f, 0.f};

    int nT = (m0 + 128) / KT;
    for (int t = 0; t < nT; t++) {
        int kt0 = t * KT;
        __syncthreads();   // previous tile fully consumed before overwrite

        // ---- cooperative K/V load + tf32 hi/lo split (V transposed) ----
#pragma unroll
        for (int r = 0; r < 2; r++) {
            int f4 = tid * 2 + r;            // 0..511 float4s = 2048 floats
            int key = f4 >> 4;
            int d = (f4 & 15) * 4;
            const float* Kg = g_K + ((size_t)h * SEQ + kt0 + key) * HD + d;
            const float* Vg = g_V + ((size_t)h * SEQ + kt0 + key) * HD + d;
            float4 kv = *(const float4*)Kg;
            float4 vv = *(const float4*)Vg;
            float kt[4] = {kv.x, kv.y, kv.z, kv.w};
            float vt[4] = {vv.x, vv.y, vv.z, vv.w};
            float khv[4], klv[4];
#pragma unroll
            for (int i = 0; i < 4; i++) {
                float hf = __uint_as_float(f2tf32(kt[i]));
                khv[i] = hf;
                klv[i] = kt[i] - hf;
            }
            *(float4*)&Kh[key][d] = make_float4(khv[0], khv[1], khv[2], khv[3]);
            *(float4*)&Kl[key][d] = make_float4(klv[0], klv[1], klv[2], klv[3]);
#pragma unroll
            for (int i = 0; i < 4; i++) {
                float hf = __uint_as_float(f2tf32(vt[i]));
                VTh[d + i][key] = hf;
                VTl[d + i][key] = vt[i] - hf;
            }
        }
        __syncthreads();

        if (kt0 <= q0w + 15) {   // warp-level causal tile skip (no barriers inside)
            // ---- S = Q @ K^T via 3xTF32 ----
            float s[4][4];
#pragma unroll
            for (int nn = 0; nn < 4; nn++)
#pragma unroll
                for (int i = 0; i < 4; i++) s[nn][i] = 0.f;
#pragma unroll
            for (int kk = 0; kk < 8; kk++) {
#pragma unroll
                for (int nn = 0; nn < 4; nn++) {
                    unsigned bh[2], bl[2];
                    bh[0] = __float_as_uint(Kh[nn * 8 + g][kk * 8 + c]);
                    bh[1] = __float_as_uint(Kh[nn * 8 + g][kk * 8 + c + 4]);
                    bl[0] = __float_as_uint(Kl[nn * 8 + g][kk * 8 + c]);
                    bl[1] = __float_as_uint(Kl[nn * 8 + g][kk * 8 + c + 4]);
                    mma_tf32(s[nn], qh[kk], bh);
                    mma_tf32(s[nn], qh[kk], bl);
                    mma_tf32(s[nn], ql[kk], bh);
                }
            }

            // ---- causal mask + online softmax ----
            float tmax[2] = {-INFINITY, -INFINITY};
#pragma unroll
            for (int nn = 0; nn < 4; nn++) {
#pragma unroll
                for (int i = 0; i < 4; i++) {
                    int qrow = q0w + g + ((i >> 1) << 3);
                    int kcol = kt0 + nn * 8 + 2 * c + (i & 1);
                    if (kcol > qrow) s[nn][i] = -INFINITY;
                    tmax[i >> 1] = fmaxf(tmax[i >> 1], s[nn][i]);
                }
            }
#pragma unroll
            for (int off = 1; off <= 2; off <<= 1) {
                tmax[0] = fmaxf(tmax[0], __shfl_xor_sync(0xffffffffu, tmax[0], off));
                tmax[1] = fmaxf(tmax[1], __shfl_xor_sync(0xffffffffu, tmax[1], off));
            }
            float mnew0 = fmaxf(mrow[0], tmax[0]);
            float mnew1 = fmaxf(mrow[1], tmax[1]);
            float corr0 = __expf(mrow[0] - mnew0);
            float corr1 = __expf(mrow[1] - mnew1);
            mrow[0] = mnew0; mrow[1] = mnew1;

            float rsum[2] = {0.f, 0.f};
#pragma unroll
            for (int nn = 0; nn < 4; nn++) {
#pragma unroll
                for (int i = 0; i < 4; i++) {
                    float p = __expf(s[nn][i] - ((i >> 1) ? mnew1 : mnew0));
                    s[nn][i] = p;
                    rsum[i >> 1] += p;
                }
            }
#pragma unroll
            for (int off = 1; off <= 2; off <<= 1) {
                rsum[0] += __shfl_xor_sync(0xffffffffu, rsum[0], off);
                rsum[1] += __shfl_xor_sync(0xffffffffu, rsum[1], off);
            }
            lrow[0] = lrow[0] * corr0 + rsum[0];
            lrow[1] = lrow[1] * corr1 + rsum[1];
#pragma unroll
            for (int nn = 0; nn < 8; nn++) {
                o[nn][0] *= corr0; o[nn][1] *= corr0;
                o[nn][2] *= corr1; o[nn][3] *= corr1;
            }

            // ---- O += P @ V via 3xTF32 (P C-frag -> A-frag by shuffles) ----
            int src0 = (lane & ~3) | (c >> 1);
            int src2 = src0 + 2;
#pragma unroll
            for (int kk = 0; kk < 4; kk++) {
                float x0 = __shfl_sync(0xffffffffu, s[kk][0], src0);
                float x1 = __shfl_sync(0xffffffffu, s[kk][1], src0);
                float y0 = __shfl_sync(0xffffffffu, s[kk][2], src0);
                float y1 = __shfl_sync(0xffffffffu, s[kk][3], src0);
                float z0 = __shfl_sync(0xffffffffu, s[kk][0], src2);
                float z1 = __shfl_sync(0xffffffffu, s[kk][1], src2);
                float u0 = __shfl_sync(0xffffffffu, s[kk][2], src2);
                float u1 = __shfl_sync(0xffffffffu, s[kk][3], src2);
                float af[4];
                af[0] = (c & 1) ? x1 : x0;
                af[1] = (c & 1) ? y1 : y0;
                af[2] = (c & 1) ? z1 : z0;
                af[3] = (c & 1) ? u1 : u0;
                unsigned ah[4], al[4];
#pragma unroll
                for (int i = 0; i < 4; i++) {
                    unsigned hi = f2tf32(af[i]);
                    ah[i] = hi;
                    al[i] = __float_as_uint(af[i] - __uint_as_float(hi));
                }
#pragma unroll
                for (int nn = 0; nn < 8; nn++) {
                    unsigned bh[2], bl[2];
                    bh[0] = __float_as_uint(VTh[nn * 8 + g][kk * 8 + c]);
                    bh[1] = __float_as_uint(VTh[nn * 8 + g][kk * 8 + c + 4]);
                    bl[0] = __float_as_uint(VTl[nn * 8 + g][kk * 8 + c]);
                    bl[1] = __float_as_uint(VTl[nn * 8 + g][kk * 8 + c + 4]);
                    mma_tf32(o[nn], ah, bh);
                    mma_tf32(o[nn], ah, bl);
                    mma_tf32(o[nn], al, bh);
                }
            }
        }
    }

    // ---- normalize + write O (row-major [s][dim], head offset) ----
    float inv0 = 1.f / lrow[0];
    float inv1 = 1.f / lrow[1];
#pragma unroll
    for (int nn = 0; nn < 8; nn++) {
        int d = h * HD + nn * 8 + 2 * c;
        float2 r0 = make_float2(o[nn][0] * inv0, o[nn][1] * inv0);
        float2 r1 = make_float2(o[nn][2] * inv1, o[nn][3] * inv1);
        *(float2*)(g_O + (size_t)(q0w + g) * DIM + d) = r0;
        *(float2*)(g_O + (size_t)(q0w + g + 8) * DIM + d) = r1;
    }
}

// ---------------- LayerNorm over last dim (1024) ------------------------
__global__ __launch_bounds__(256)
void layernorm_kernel(const float* __restrict__ gamma,
                      const float* __restrict__ beta,
                      float* __restrict__ Y) {
    int r = blockIdx.x;
    const float* x = g_att + (size_t)r * DIM;
    int tid = threadIdx.x;

    float s = 0.f, s2 = 0.f;
#pragma unroll
    for (int it = 0; it < DIM / 256; it++) {
        float v = x[tid + it * 256];
        s += v;
        s2 += v * v;
    }
#pragma unroll
    for (int off = 16; off; off >>= 1) {
        s  += __shfl_xor_sync(0xffffffffu, s, off);
        s2 += __shfl_xor_sync(0xffffffffu, s2, off);
    }
    __shared__ float ws[8], ws2[8];
    int w = tid >> 5, lane = tid & 31;
    if (lane == 0) { ws[w] = s; ws2[w] = s2; }
    __syncthreads();
    float S1 = 0.f, S2 = 0.f;
#pragma unroll
    for (int i = 0; i < 8; i++) { S1 += ws[i]; S2 += ws2[i]; }

    float mu  = S1 * (1.f / DIM);
    float var = S2 * (1.f / DIM) - mu * mu;
    float inv = rsqrtf(var + 1e-5f);
#pragma unroll
    for (int it = 0; it < DIM / 256; it++) {
        int j = tid + it * 256;
        float v = x[j];
        Y[(size_t)r * DIM + j] = (v - mu) * inv * gamma[j] + beta[j];
    }
}

// ---------------- launch (pure kernel launches, no runtime API) ---------
extern "C" void kernel_launch(void* const* d_in, const int* in_sizes, int n_in,
                              void* d_out, int out_size) {
    const float* x     = (const float*)d_in[0];
    const float* Wqkv  = (const float*)d_in[1];
    const float* bqkv  = (const float*)d_in[2];
    const float* Wo    = (const float*)d_in[3];
    const float* bo    = (const float*)d_in[4];
    const float* gamma = (const float*)d_in[5];
    const float* beta  = (const float*)d_in[6];
    float* out = (float*)d_out;

    rope_tables_kernel<<<(SEQ * 512) / 256, 256>>>();
    sgemm_qkv_kernel<<<dim3(3 * DIM / 128, SEQ / 128), 256>>>(x, Wqkv, bqkv);
    rope_scatter_kernel<<<(SEQ * DIM) / 256, 256>>>();
    flash_mma_kernel<<<dim3(SEQ / 128, NH), 256>>>();
    sgemm_out_kernel<<<dim3(DIM / 128, SEQ / 128), 256>>>(Wo, bo);
    layernorm_kernel<<<SEQ, 256>>>(gamma, beta, out);
}